// round 1
// baseline (speedup 1.0000x reference)
#include <cuda_runtime.h>
#include <math.h>

// Problem constants
#define B_    8
#define H_    8
#define LQ_   512
#define T_    8192
#define DIM_  256
#define HD_   32
#define MAXREL_ 128

// ---------------- scratch (static device globals; no runtime allocation) ----------------
__device__ float g_Q[B_ * LQ_ * DIM_];     // scaled Q projection      (4 MB)
__device__ float g_K[B_ * T_ * DIM_];      // K projection             (64 MB)
__device__ float g_V[B_ * T_ * DIM_];      // V projection             (64 MB)
__device__ float g_mask[LQ_ * T_];         // time mask                (16 MB)
__device__ float g_ctx[B_ * LQ_ * DIM_];   // attention context        (4 MB)

// ---------------- mask precompute ----------------
__global__ void mask_kernel(const float* __restrict__ rel_bias,
                            const float* __restrict__ mask_scale,
                            float* __restrict__ mask) {
    int idx = blockIdx.x * blockDim.x + threadIdx.x;
    if (idx >= LQ_ * T_) return;
    int i = idx >> 13;          // / 8192
    int t = idx & (T_ - 1);
    const float step = 8191.0f / 511.0f;        // linspace delta in fp32
    float tau = (float)i * step;
    float dt  = (float)t - tau;
    float dtc = fminf(fmaxf(dt, -(float)MAXREL_), (float)MAXREL_);
    int bi = (int)dtc + MAXREL_;                // truncation toward zero, matches astype(int32)
    float bias = rel_bias[bi];
    float z = dt * (1.0f / 64.0f);              // TIME_SIGMA = 64
    float lg = logf(expf(-0.5f * z * z) + 1e-6f);
    mask[idx] = mask_scale[0] * (bias + lg);
}

// ---------------- generic projection GEMM: out[r,c] = scale*(dot(in[r,:],W[c,:]) + bias[c]) ----------------
// block: 256 threads, 16 rows per block, each thread owns one output column for all 16 rows.
__global__ void proj_kernel(const float* __restrict__ in,
                            const float* __restrict__ W,
                            const float* __restrict__ bias,
                            float* __restrict__ out,
                            float scale) {
    __shared__ float in_s[16][DIM_];     // 16 KB
    __shared__ float w_s[DIM_][33];      // 33.8 KB, padded: conflict-free by column
    int tid = threadIdx.x;
    int row0 = blockIdx.x * 16;

    #pragma unroll
    for (int it = 0; it < 16; it++) {
        int idx = tid + it * 256;
        in_s[idx >> 8][idx & 255] = in[row0 * DIM_ + idx];
    }

    float acc[16];
    #pragma unroll
    for (int r = 0; r < 16; r++) acc[r] = 0.0f;

    for (int k0 = 0; k0 < DIM_; k0 += 32) {
        __syncthreads();   // in_s ready (first iter) / previous compute done before w_s overwrite
        #pragma unroll
        for (int it = 0; it < 32; it++) {
            int idx = tid + it * 256;                 // 256*32 elements
            int c = idx >> 5, kk = idx & 31;
            w_s[c][kk] = W[c * DIM_ + k0 + kk];
        }
        __syncthreads();
        #pragma unroll
        for (int kk = 0; kk < 32; kk++) {
            float w = w_s[tid][kk];
            #pragma unroll
            for (int r = 0; r < 16; r++)
                acc[r] += in_s[r][k0 + kk] * w;
        }
    }

    float bv = bias[tid];
    #pragma unroll
    for (int r = 0; r < 16; r++)
        out[(row0 + r) * DIM_ + tid] = scale * (acc[r] + bv);
}

// ---------------- flash attention ----------------
// grid: B*H*(Lq/32) = 1024 blocks; block: 128 threads (4 warps), each warp owns 8 q-rows.
// lane index == head-dim index (HD=32).
__global__ void attn_kernel(const float* __restrict__ Q,
                            const float* __restrict__ K,
                            const float* __restrict__ V,
                            const float* __restrict__ mask,
                            float* __restrict__ ctx) {
    const int QT = 32, KT = 32;
    __shared__ float K_s[KT][HD_ + 1];
    __shared__ float V_s[KT][HD_ + 1];
    __shared__ float M_s[QT][KT + 1];

    int tid  = threadIdx.x;
    int lane = tid & 31;
    int warp = tid >> 5;
    int blk = blockIdx.x;
    int qt = blk & 15;
    int h  = (blk >> 4) & 7;
    int b  = blk >> 7;
    int q0 = qt * QT;
    int qbase = warp * 8;

    float qreg[8], m[8], l[8], o[8];
    #pragma unroll
    for (int ii = 0; ii < 8; ii++) {
        int qg = q0 + qbase + ii;
        qreg[ii] = Q[(b * LQ_ + qg) * DIM_ + h * HD_ + lane];  // scale already folded in
        m[ii] = -INFINITY; l[ii] = 0.0f; o[ii] = 0.0f;
    }

    for (int t0 = 0; t0 < T_; t0 += KT) {
        #pragma unroll
        for (int it = 0; it < 8; it++) {
            int idx = tid + it * 128;           // 1024 = 32*32
            int j = idx >> 5, d = idx & 31;
            K_s[j][d] = K[(b * T_ + t0 + j) * DIM_ + h * HD_ + d];
            V_s[j][d] = V[(b * T_ + t0 + j) * DIM_ + h * HD_ + d];
            M_s[j][d] = mask[(q0 + j) * T_ + t0 + d];   // row j = q-row in tile, d = key col
        }
        __syncthreads();

        // scores: s[ii] = mask + sum_d Qs[i][d]*K[lane][d]
        float s[8];
        #pragma unroll
        for (int ii = 0; ii < 8; ii++) s[ii] = M_s[qbase + ii][lane];
        #pragma unroll
        for (int d = 0; d < HD_; d++) {
            float kd = K_s[lane][d];
            #pragma unroll
            for (int ii = 0; ii < 8; ii++)
                s[ii] += __shfl_sync(0xffffffffu, qreg[ii], d) * kd;
        }

        // online softmax update per row
        float p[8];
        #pragma unroll
        for (int ii = 0; ii < 8; ii++) {
            float smax = s[ii];
            #pragma unroll
            for (int off = 16; off; off >>= 1)
                smax = fmaxf(smax, __shfl_xor_sync(0xffffffffu, smax, off));
            float mnew = fmaxf(m[ii], smax);
            float pv = expf(s[ii] - mnew);
            float psum = pv;
            #pragma unroll
            for (int off = 16; off; off >>= 1)
                psum += __shfl_xor_sync(0xffffffffu, psum, off);
            float alpha = expf(m[ii] - mnew);
            l[ii] = l[ii] * alpha + psum;
            o[ii] *= alpha;
            m[ii] = mnew;
            p[ii] = pv;
        }

        // o[ii][lane=d] += sum_j p[ii][j] * V[j][d]
        #pragma unroll
        for (int j = 0; j < KT; j++) {
            float v = V_s[j][lane];
            #pragma unroll
            for (int ii = 0; ii < 8; ii++)
                o[ii] += __shfl_sync(0xffffffffu, p[ii], j) * v;
        }
        __syncthreads();
    }

    #pragma unroll
    for (int ii = 0; ii < 8; ii++) {
        int qg = q0 + qbase + ii;
        ctx[(b * LQ_ + qg) * DIM_ + h * HD_ + lane] = o[ii] / l[ii];
    }
}

// ---------------- launch ----------------
extern "C" void kernel_launch(void* const* d_in, const int* in_sizes, int n_in,
                              void* d_out, int out_size) {
    const float* q          = (const float*)d_in[0];   // [8,512,256]
    const float* kv         = (const float*)d_in[1];   // [8,8192,256]
    const float* in_proj_w  = (const float*)d_in[2];   // [768,256]
    const float* in_proj_b  = (const float*)d_in[3];   // [768]
    const float* out_proj_w = (const float*)d_in[4];   // [256,256]
    const float* out_proj_b = (const float*)d_in[5];   // [256]
    const float* rel_bias   = (const float*)d_in[6];   // [257]
    const float* mask_scale = (const float*)d_in[7];   // [1]
    float* out = (float*)d_out;

    float *pQ, *pK, *pV, *pM, *pC;
    cudaGetSymbolAddress((void**)&pQ, g_Q);
    cudaGetSymbolAddress((void**)&pK, g_K);
    cudaGetSymbolAddress((void**)&pV, g_V);
    cudaGetSymbolAddress((void**)&pM, g_mask);
    cudaGetSymbolAddress((void**)&pC, g_ctx);

    const float* wq = in_proj_w;
    const float* wk = in_proj_w + DIM_ * DIM_;
    const float* wv = in_proj_w + 2 * DIM_ * DIM_;
    const float* bq = in_proj_b;
    const float* bk = in_proj_b + DIM_;
    const float* bv = in_proj_b + 2 * DIM_;

    const float attn_scale = 0.17677669529663687f;  // 1/sqrt(32)

    // 1) mask
    mask_kernel<<<(LQ_ * T_) / 256, 256>>>(rel_bias, mask_scale, pM);
    // 2) projections (Q carries the attention scale)
    proj_kernel<<<(B_ * LQ_) / 16, 256>>>(q,  wq, bq, pQ, attn_scale);
    proj_kernel<<<(B_ * T_)  / 16, 256>>>(kv, wk, bk, pK, 1.0f);
    proj_kernel<<<(B_ * T_)  / 16, 256>>>(kv, wv, bv, pV, 1.0f);
    // 3) flash attention
    attn_kernel<<<B_ * H_ * (LQ_ / 32), 128>>>(pQ, pK, pV, pM, pC);
    // 4) output projection
    proj_kernel<<<(B_ * LQ_) / 16, 256>>>(pC, out_proj_w, out_proj_b, out, 1.0f);
}

// round 2
// speedup vs baseline: 3.0658x; 3.0658x over previous
#include <cuda_runtime.h>
#include <math.h>

#define B_    8
#define H_    8
#define LQ_   512
#define T_    8192
#define DIM_  256
#define HD_   32
#define MAXREL_ 128

// ---------------- scratch ----------------
__device__ float g_Q[B_ * LQ_ * DIM_];        // scaled Q projection  (4 MB)
__device__ float g_KV[B_ * T_ * 2 * DIM_];    // fused K|V projection (128 MB), row = [K(256) | V(256)]
__device__ float g_mask[LQ_ * T_];            // time mask            (16 MB)
__device__ float g_ctx[B_ * LQ_ * DIM_];      // attention context    (4 MB)

// ---------------- mask precompute ----------------
__global__ void mask_kernel(const float* __restrict__ rel_bias,
                            const float* __restrict__ mask_scale,
                            float* __restrict__ mask) {
    int idx = blockIdx.x * blockDim.x + threadIdx.x;
    int i = idx >> 13;
    int t = idx & (T_ - 1);
    const float step = 8191.0f / 511.0f;
    float tau = (float)i * step;
    float dt  = (float)t - tau;
    float dtc = fminf(fmaxf(dt, -(float)MAXREL_), (float)MAXREL_);
    int bi = (int)dtc + MAXREL_;
    float bias = rel_bias[bi];
    float z = dt * (1.0f / 64.0f);
    float lg = __logf(__expf(-0.5f * z * z) + 1e-6f);
    mask[idx] = mask_scale[0] * (bias + lg);
}

// ---------------- generic GEMM: out[r,c] = scale*(dot(A[r,:256], W[c,:256]) + bias[c]) ----------------
// grid (M/64, N/64), block 256 = 16x16, thread computes 4x4.
#define KBLK 16
__global__ void gemm_kernel(const float* __restrict__ A,
                            const float* __restrict__ W,
                            const float* __restrict__ bias,
                            float* __restrict__ out,
                            int ldo, float scale) {
    __shared__ float A_s[KBLK][68];   // [k][row], padded (68*4=272B, 16B-aligned rows)
    __shared__ float W_s[KBLK][68];   // [k][col]
    int tid = threadIdx.x;
    int tx = tid & 15, ty = tid >> 4;
    int row0 = blockIdx.x * 64;
    int col0 = blockIdx.y * 64;

    int lrow = tid >> 2;            // 0..63
    int lk4  = (tid & 3) * 4;       // 0,4,8,12

    float acc[4][4];
    #pragma unroll
    for (int i = 0; i < 4; i++)
        #pragma unroll
        for (int j = 0; j < 4; j++) acc[i][j] = 0.0f;

    for (int k0 = 0; k0 < 256; k0 += KBLK) {
        float4 a4 = *(const float4*)&A[(row0 + lrow) * 256 + k0 + lk4];
        float4 w4 = *(const float4*)&W[(col0 + lrow) * 256 + k0 + lk4];
        __syncthreads();
        A_s[lk4 + 0][lrow] = a4.x; A_s[lk4 + 1][lrow] = a4.y;
        A_s[lk4 + 2][lrow] = a4.z; A_s[lk4 + 3][lrow] = a4.w;
        W_s[lk4 + 0][lrow] = w4.x; W_s[lk4 + 1][lrow] = w4.y;
        W_s[lk4 + 2][lrow] = w4.z; W_s[lk4 + 3][lrow] = w4.w;
        __syncthreads();
        #pragma unroll
        for (int kk = 0; kk < KBLK; kk++) {
            float4 av = *(const float4*)&A_s[kk][ty * 4];
            float4 wv = *(const float4*)&W_s[kk][tx * 4];
            acc[0][0] += av.x * wv.x; acc[0][1] += av.x * wv.y; acc[0][2] += av.x * wv.z; acc[0][3] += av.x * wv.w;
            acc[1][0] += av.y * wv.x; acc[1][1] += av.y * wv.y; acc[1][2] += av.y * wv.z; acc[1][3] += av.y * wv.w;
            acc[2][0] += av.z * wv.x; acc[2][1] += av.z * wv.y; acc[2][2] += av.z * wv.z; acc[2][3] += av.z * wv.w;
            acc[3][0] += av.w * wv.x; acc[3][1] += av.w * wv.y; acc[3][2] += av.w * wv.z; acc[3][3] += av.w * wv.w;
        }
    }

    float4 bv = *(const float4*)&bias[col0 + tx * 4];
    #pragma unroll
    for (int i = 0; i < 4; i++) {
        float4 r;
        r.x = scale * (acc[i][0] + bv.x);
        r.y = scale * (acc[i][1] + bv.y);
        r.z = scale * (acc[i][2] + bv.z);
        r.w = scale * (acc[i][3] + bv.w);
        *(float4*)&out[(row0 + ty * 4 + i) * ldo + col0 + tx * 4] = r;
    }
}

// ---------------- flash attention, smem-GEMM style ----------------
// grid (8 qtiles, 8 heads, 8 batch), block 256 = 16x16.
// Per tile: 64 q x 64 k scores (4x4 per thread), then PV with 4q x 2d per thread.
__global__ void attn_kernel(const float* __restrict__ Q,
                            const float* __restrict__ KV,
                            const float* __restrict__ mask,
                            float* __restrict__ ctx) {
    __shared__ float Q_s[32][68];    // [d][q]
    __shared__ float K_s[32][68];    // [d][k]
    __shared__ float V_s[64][36];    // [k][d]
    __shared__ float MP_s[64][68];   // mask[q][k], overwritten in-place by P[q][k]

    int tid = threadIdx.x;
    int tx = tid & 15, ty = tid >> 4;
    int q0 = blockIdx.x * 64;
    int h  = blockIdx.y;
    int b  = blockIdx.z;

    // load Q tile (transposed to [d][q])
    #pragma unroll
    for (int it = 0; it < 2; it++) {
        int idx = tid + it * 256;                 // 0..511
        int qq = idx >> 3, d4 = (idx & 7) * 4;
        float4 v = *(const float4*)&Q[(b * LQ_ + q0 + qq) * DIM_ + h * HD_ + d4];
        Q_s[d4 + 0][qq] = v.x; Q_s[d4 + 1][qq] = v.y;
        Q_s[d4 + 2][qq] = v.z; Q_s[d4 + 3][qq] = v.w;
    }

    float m[4], l[4], o[4][2];
    #pragma unroll
    for (int i = 0; i < 4; i++) { m[i] = -1e30f; l[i] = 0.0f; o[i][0] = 0.0f; o[i][1] = 0.0f; }

    for (int t0 = 0; t0 < T_; t0 += 64) {
        // stage K (transposed), V (direct), mask tiles
        #pragma unroll
        for (int it = 0; it < 2; it++) {
            int idx = tid + it * 256;
            int kk = idx >> 3, d4 = (idx & 7) * 4;
            const float* kvrow = &KV[(size_t)(b * T_ + t0 + kk) * (2 * DIM_) + h * HD_];
            float4 kv4 = *(const float4*)&kvrow[d4];
            K_s[d4 + 0][kk] = kv4.x; K_s[d4 + 1][kk] = kv4.y;
            K_s[d4 + 2][kk] = kv4.z; K_s[d4 + 3][kk] = kv4.w;
            float4 vv4 = *(const float4*)&kvrow[DIM_ + d4];
            *(float4*)&V_s[kk][d4] = vv4;
        }
        #pragma unroll
        for (int it = 0; it < 4; it++) {
            int idx = tid + it * 256;                 // 0..1023
            int qq = idx >> 4, k4 = (idx & 15) * 4;
            *(float4*)&MP_s[qq][k4] = *(const float4*)&mask[(q0 + qq) * T_ + t0 + k4];
        }
        __syncthreads();

        // scores = mask + Q.K
        float s[4][4];
        #pragma unroll
        for (int qi = 0; qi < 4; qi++) {
            float4 mv = *(const float4*)&MP_s[ty * 4 + qi][tx * 4];
            s[qi][0] = mv.x; s[qi][1] = mv.y; s[qi][2] = mv.z; s[qi][3] = mv.w;
        }
        #pragma unroll
        for (int d = 0; d < HD_; d++) {
            float4 qv = *(const float4*)&Q_s[d][ty * 4];
            float4 kv4 = *(const float4*)&K_s[d][tx * 4];
            s[0][0] += qv.x * kv4.x; s[0][1] += qv.x * kv4.y; s[0][2] += qv.x * kv4.z; s[0][3] += qv.x * kv4.w;
            s[1][0] += qv.y * kv4.x; s[1][1] += qv.y * kv4.y; s[1][2] += qv.y * kv4.z; s[1][3] += qv.y * kv4.w;
            s[2][0] += qv.z * kv4.x; s[2][1] += qv.z * kv4.y; s[2][2] += qv.z * kv4.z; s[2][3] += qv.z * kv4.w;
            s[3][0] += qv.w * kv4.x; s[3][1] += qv.w * kv4.y; s[3][2] += qv.w * kv4.z; s[3][3] += qv.w * kv4.w;
        }

        // online softmax over the 64-key tile; row spans 16 lanes (same ty group)
        #pragma unroll
        for (int qi = 0; qi < 4; qi++) {
            float tmax = fmaxf(fmaxf(s[qi][0], s[qi][1]), fmaxf(s[qi][2], s[qi][3]));
            #pragma unroll
            for (int off = 8; off; off >>= 1)
                tmax = fmaxf(tmax, __shfl_xor_sync(0xffffffffu, tmax, off));
            float mnew = fmaxf(m[qi], tmax);
            float psum = 0.0f;
            #pragma unroll
            for (int kj = 0; kj < 4; kj++) {
                s[qi][kj] = __expf(s[qi][kj] - mnew);
                psum += s[qi][kj];
            }
            #pragma unroll
            for (int off = 8; off; off >>= 1)
                psum += __shfl_xor_sync(0xffffffffu, psum, off);
            float alpha = __expf(m[qi] - mnew);
            l[qi] = l[qi] * alpha + psum;
            o[qi][0] *= alpha; o[qi][1] *= alpha;
            m[qi] = mnew;
        }

        // write P over mask tile (same [q][k] slots this thread read)
        #pragma unroll
        for (int qi = 0; qi < 4; qi++) {
            float4 p4; p4.x = s[qi][0]; p4.y = s[qi][1]; p4.z = s[qi][2]; p4.w = s[qi][3];
            *(float4*)&MP_s[ty * 4 + qi][tx * 4] = p4;
        }
        __syncthreads();

        // o[q][d] += P[q][k] * V[k][d], thread owns 4q x 2d (d = tx*2, tx*2+1)
        #pragma unroll
        for (int k0 = 0; k0 < 64; k0 += 4) {
            float2 v0 = *(const float2*)&V_s[k0 + 0][tx * 2];
            float2 v1 = *(const float2*)&V_s[k0 + 1][tx * 2];
            float2 v2 = *(const float2*)&V_s[k0 + 2][tx * 2];
            float2 v3 = *(const float2*)&V_s[k0 + 3][tx * 2];
            #pragma unroll
            for (int qi = 0; qi < 4; qi++) {
                float4 p4 = *(const float4*)&MP_s[ty * 4 + qi][k0];
                o[qi][0] += p4.x * v0.x + p4.y * v1.x + p4.z * v2.x + p4.w * v3.x;
                o[qi][1] += p4.x * v0.y + p4.y * v1.y + p4.z * v2.y + p4.w * v3.y;
            }
        }
        __syncthreads();
    }

    #pragma unroll
    for (int qi = 0; qi < 4; qi++) {
        float inv = 1.0f / l[qi];
        float2 r; r.x = o[qi][0] * inv; r.y = o[qi][1] * inv;
        *(float2*)&ctx[(b * LQ_ + q0 + ty * 4 + qi) * DIM_ + h * HD_ + tx * 2] = r;
    }
}

// ---------------- launch ----------------
extern "C" void kernel_launch(void* const* d_in, const int* in_sizes, int n_in,
                              void* d_out, int out_size) {
    const float* q          = (const float*)d_in[0];
    const float* kv         = (const float*)d_in[1];
    const float* in_proj_w  = (const float*)d_in[2];
    const float* in_proj_b  = (const float*)d_in[3];
    const float* out_proj_w = (const float*)d_in[4];
    const float* out_proj_b = (const float*)d_in[5];
    const float* rel_bias   = (const float*)d_in[6];
    const float* mask_scale = (const float*)d_in[7];
    float* out = (float*)d_out;

    float *pQ, *pKV, *pM, *pC;
    cudaGetSymbolAddress((void**)&pQ,  g_Q);
    cudaGetSymbolAddress((void**)&pKV, g_KV);
    cudaGetSymbolAddress((void**)&pM,  g_mask);
    cudaGetSymbolAddress((void**)&pC,  g_ctx);

    const float attn_scale = 0.17677669529663687f;  // 1/sqrt(32)

    mask_kernel<<<(LQ_ * T_) / 256, 256>>>(rel_bias, mask_scale, pM);

    // Q projection (scale folded)
    gemm_kernel<<<dim3((B_ * LQ_) / 64, DIM_ / 64), 256>>>(
        q, in_proj_w, in_proj_b, pQ, DIM_, attn_scale);

    // fused K|V projection: W rows 256..767 and biases 256..767 are contiguous
    gemm_kernel<<<dim3((B_ * T_) / 64, (2 * DIM_) / 64), 256>>>(
        kv, in_proj_w + DIM_ * DIM_, in_proj_b + DIM_, pKV, 2 * DIM_, 1.0f);

    attn_kernel<<<dim3(LQ_ / 64, H_, B_), 256>>>(pQ, pKV, pM, pC);

    gemm_kernel<<<dim3((B_ * LQ_) / 64, DIM_ / 64), 256>>>(
        pC, out_proj_w, out_proj_b, out, DIM_, 1.0f);
}

// round 3
// speedup vs baseline: 7.6206x; 2.4857x over previous
#include <cuda_runtime.h>
#include <math.h>

#define B_    8
#define H_    8
#define LQ_   512
#define T_    8192
#define DIM_  256
#define HD_   32
#define MAXREL_ 128

// ---------------- scratch ----------------
__device__ float g_Q[B_ * LQ_ * DIM_];        // scaled Q projection  (4 MB)
__device__ float g_KV[B_ * T_ * 2 * DIM_];    // fused K|V projection (128 MB)
__device__ float g_mask[LQ_ * T_];            // time mask            (16 MB)
__device__ float g_ctx[B_ * LQ_ * DIM_];      // attention context    (4 MB)

// ---------------- tf32 mma helpers ----------------
__device__ __forceinline__ unsigned f2tf32(float x) {
    unsigned r; asm("cvt.rna.tf32.f32 %0, %1;" : "=r"(r) : "f"(x)); return r;
}
__device__ __forceinline__ void mma_tf32(float c[4], const unsigned a[4], const unsigned b[2]) {
    asm volatile("mma.sync.aligned.m16n8k8.row.col.f32.tf32.tf32.f32 "
        "{%0,%1,%2,%3}, {%4,%5,%6,%7}, {%8,%9}, {%0,%1,%2,%3};"
        : "+f"(c[0]), "+f"(c[1]), "+f"(c[2]), "+f"(c[3])
        : "r"(a[0]), "r"(a[1]), "r"(a[2]), "r"(a[3]), "r"(b[0]), "r"(b[1]));
}

// ---------------- mask precompute ----------------
__global__ void mask_kernel(const float* __restrict__ rel_bias,
                            const float* __restrict__ mask_scale,
                            float* __restrict__ mask) {
    int idx = blockIdx.x * blockDim.x + threadIdx.x;
    int i = idx >> 13;
    int t = idx & (T_ - 1);
    const float step = 8191.0f / 511.0f;
    float tau = (float)i * step;
    float dt  = (float)t - tau;
    float dtc = fminf(fmaxf(dt, -(float)MAXREL_), (float)MAXREL_);
    int bi = (int)dtc + MAXREL_;
    float bias = rel_bias[bi];
    float z = dt * (1.0f / 64.0f);
    float lg = __logf(__expf(-0.5f * z * z) + 1e-6f);
    mask[idx] = mask_scale[0] * (bias + lg);
}

// ---------------- tf32 GEMM: out[r,c] = scale*(dot(A[r,:256], W[c,:256]) + bias[c]) ----------------
// block tile 128x128, K=256 in 32-chunks; 8 warps as 4(m) x 2(n); warp tile 32x64.
__global__ void gemm_mma(const float* __restrict__ A, const float* __restrict__ W,
                         const float* __restrict__ bias, float* __restrict__ out,
                         int ldo, float scale) {
    __shared__ unsigned As[128][36];   // tf32 bits, row-major [m][k], pad 4
    __shared__ unsigned Ws[128][36];   // [n][k]
    int tid = threadIdx.x;
    int lane = tid & 31, warp = tid >> 5;
    int wm = warp >> 1, wn = warp & 1;
    int g = lane >> 2, tig = lane & 3;
    int row0 = blockIdx.x * 128, col0 = blockIdx.y * 128;

    float c[2][8][4];
    #pragma unroll
    for (int i = 0; i < 2; i++)
        #pragma unroll
        for (int j = 0; j < 8; j++)
            #pragma unroll
            for (int v = 0; v < 4; v++) c[i][j][v] = 0.0f;

    int sm  = tid >> 3;          // 0..31
    int sk4 = (tid & 7) * 4;     // 0..28

    for (int k0 = 0; k0 < 256; k0 += 32) {
        __syncthreads();
        #pragma unroll
        for (int it = 0; it < 4; it++) {
            int r = sm + it * 32;
            float4 a4 = *(const float4*)&A[(size_t)(row0 + r) * 256 + k0 + sk4];
            float4 w4 = *(const float4*)&W[(size_t)(col0 + r) * 256 + k0 + sk4];
            uint4 au; au.x = f2tf32(a4.x); au.y = f2tf32(a4.y); au.z = f2tf32(a4.z); au.w = f2tf32(a4.w);
            uint4 wu; wu.x = f2tf32(w4.x); wu.y = f2tf32(w4.y); wu.z = f2tf32(w4.z); wu.w = f2tf32(w4.w);
            *(uint4*)&As[r][sk4] = au;
            *(uint4*)&Ws[r][sk4] = wu;
        }
        __syncthreads();
        #pragma unroll
        for (int kk = 0; kk < 32; kk += 8) {
            unsigned af[2][4], bf[8][2];
            #pragma unroll
            for (int i = 0; i < 2; i++) {
                int mr = wm * 32 + i * 16;
                af[i][0] = As[mr + g][kk + tig];
                af[i][1] = As[mr + g + 8][kk + tig];
                af[i][2] = As[mr + g][kk + tig + 4];
                af[i][3] = As[mr + g + 8][kk + tig + 4];
            }
            #pragma unroll
            for (int j = 0; j < 8; j++) {
                int nc = wn * 64 + j * 8;
                bf[j][0] = Ws[nc + g][kk + tig];
                bf[j][1] = Ws[nc + g][kk + tig + 4];
            }
            #pragma unroll
            for (int i = 0; i < 2; i++)
                #pragma unroll
                for (int j = 0; j < 8; j++)
                    mma_tf32(c[i][j], af[i], bf[j]);
        }
    }

    #pragma unroll
    for (int j = 0; j < 8; j++) {
        int colg = col0 + wn * 64 + j * 8 + 2 * tig;
        float2 bv = *(const float2*)&bias[colg];
        #pragma unroll
        for (int i = 0; i < 2; i++) {
            int rowg = row0 + wm * 32 + i * 16 + g;
            float2 r0, r1;
            r0.x = scale * (c[i][j][0] + bv.x);
            r0.y = scale * (c[i][j][1] + bv.y);
            r1.x = scale * (c[i][j][2] + bv.x);
            r1.y = scale * (c[i][j][3] + bv.y);
            *(float2*)&out[(size_t)rowg * ldo + colg] = r0;
            *(float2*)&out[(size_t)(rowg + 8) * ldo + colg] = r1;
        }
    }
}

// ---------------- flash attention with tf32 mma ----------------
// grid (Lq/64, H, B), 128 threads (4 warps). Warp owns 16 q-rows.
// Per 64-key tile: S(16x64) via mma with mask-initialized C frags; online softmax
// on fragments (quad shuffles); P->smem (per-warp region); PV(16x64x32) via mma.
__global__ void attn_mma(const float* __restrict__ Q,
                         const float* __restrict__ KV,
                         const float* __restrict__ mask,
                         float* __restrict__ ctx) {
    __shared__ unsigned K_s[64][36];   // [t][d] tf32
    __shared__ unsigned V_s[64][36];   // [t][d] tf32
    __shared__ unsigned P_s[64][68];   // [q][t] tf32, per-warp 16-row slices

    int tid = threadIdx.x;
    int lane = tid & 31, warp = tid >> 5;
    int g = lane >> 2, tig = lane & 3;
    int q0 = blockIdx.x * 64;
    int h  = blockIdx.y;
    int b  = blockIdx.z;
    int m0 = warp * 16;

    // resident Q fragments: A-frag for 4 k8-chunks over HD=32
    unsigned qf[4][4];
    #pragma unroll
    for (int kc = 0; kc < 4; kc++) {
        int kk = kc * 8;
        const float* qr0 = &Q[(size_t)(b * LQ_ + q0 + m0 + g) * DIM_ + h * HD_];
        const float* qr1 = qr0 + 8 * DIM_;
        qf[kc][0] = f2tf32(qr0[kk + tig]);
        qf[kc][1] = f2tf32(qr1[kk + tig]);
        qf[kc][2] = f2tf32(qr0[kk + tig + 4]);
        qf[kc][3] = f2tf32(qr1[kk + tig + 4]);
    }

    float mrow[2] = {-1e30f, -1e30f};
    float lrow[2] = {0.0f, 0.0f};
    float o[4][4];
    #pragma unroll
    for (int n = 0; n < 4; n++)
        #pragma unroll
        for (int v = 0; v < 4; v++) o[n][v] = 0.0f;

    for (int t0 = 0; t0 < T_; t0 += 64) {
        __syncthreads();
        // stage K/V tiles (64 x 32 each)
        #pragma unroll
        for (int it = 0; it < 4; it++) {
            int idx = tid + it * 128;          // 0..511
            int r = idx >> 3, d4 = (idx & 7) * 4;
            const float* base = &KV[(size_t)(b * T_ + t0 + r) * (2 * DIM_) + h * HD_ + d4];
            float4 k4 = *(const float4*)base;
            float4 v4 = *(const float4*)(base + DIM_);
            uint4 ku; ku.x = f2tf32(k4.x); ku.y = f2tf32(k4.y); ku.z = f2tf32(k4.z); ku.w = f2tf32(k4.w);
            uint4 vu; vu.x = f2tf32(v4.x); vu.y = f2tf32(v4.y); vu.z = f2tf32(v4.z); vu.w = f2tf32(v4.w);
            *(uint4*)&K_s[r][d4] = ku;
            *(uint4*)&V_s[r][d4] = vu;
        }
        __syncthreads();

        // C frags initialized with the mask tile (L2-resident)
        float c[8][4];
        {
            const float* mr0 = &mask[(size_t)(q0 + m0 + g) * T_ + t0 + 2 * tig];
            const float* mr1 = mr0 + 8 * T_;
            #pragma unroll
            for (int j = 0; j < 8; j++) {
                float2 ma = *(const float2*)&mr0[j * 8];
                float2 mb = *(const float2*)&mr1[j * 8];
                c[j][0] = ma.x; c[j][1] = ma.y; c[j][2] = mb.x; c[j][3] = mb.y;
            }
        }

        // S = mask + Q.K^T
        #pragma unroll
        for (int kc = 0; kc < 4; kc++) {
            int kk = kc * 8;
            unsigned bf[8][2];
            #pragma unroll
            for (int j = 0; j < 8; j++) {
                bf[j][0] = K_s[j * 8 + g][kk + tig];
                bf[j][1] = K_s[j * 8 + g][kk + tig + 4];
            }
            #pragma unroll
            for (int j = 0; j < 8; j++)
                mma_tf32(c[j], qf[kc], bf[j]);
        }

        // online softmax: rows g (vals 0,1) and g+8 (vals 2,3), cols span quad (tig)
        float r0 = fmaxf(c[0][0], c[0][1]);
        float r1 = fmaxf(c[0][2], c[0][3]);
        #pragma unroll
        for (int j = 1; j < 8; j++) {
            r0 = fmaxf(r0, fmaxf(c[j][0], c[j][1]));
            r1 = fmaxf(r1, fmaxf(c[j][2], c[j][3]));
        }
        r0 = fmaxf(r0, __shfl_xor_sync(0xffffffffu, r0, 1));
        r0 = fmaxf(r0, __shfl_xor_sync(0xffffffffu, r0, 2));
        r1 = fmaxf(r1, __shfl_xor_sync(0xffffffffu, r1, 1));
        r1 = fmaxf(r1, __shfl_xor_sync(0xffffffffu, r1, 2));
        float mn0 = fmaxf(mrow[0], r0);
        float mn1 = fmaxf(mrow[1], r1);
        float a0 = __expf(mrow[0] - mn0);
        float a1 = __expf(mrow[1] - mn1);
        mrow[0] = mn0; mrow[1] = mn1;

        float s0 = 0.0f, s1 = 0.0f;
        #pragma unroll
        for (int j = 0; j < 8; j++) {
            c[j][0] = __expf(c[j][0] - mn0); s0 += c[j][0];
            c[j][1] = __expf(c[j][1] - mn0); s0 += c[j][1];
            c[j][2] = __expf(c[j][2] - mn1); s1 += c[j][2];
            c[j][3] = __expf(c[j][3] - mn1); s1 += c[j][3];
        }
        s0 += __shfl_xor_sync(0xffffffffu, s0, 1);
        s0 += __shfl_xor_sync(0xffffffffu, s0, 2);
        s1 += __shfl_xor_sync(0xffffffffu, s1, 1);
        s1 += __shfl_xor_sync(0xffffffffu, s1, 2);
        lrow[0] = lrow[0] * a0 + s0;
        lrow[1] = lrow[1] * a1 + s1;
        #pragma unroll
        for (int n = 0; n < 4; n++) {
            o[n][0] *= a0; o[n][1] *= a0;
            o[n][2] *= a1; o[n][3] *= a1;
        }

        // P -> smem (per-warp rows; only warp-level sync needed)
        #pragma unroll
        for (int j = 0; j < 8; j++) {
            uint2 p01, p23;
            p01.x = f2tf32(c[j][0]); p01.y = f2tf32(c[j][1]);
            p23.x = f2tf32(c[j][2]); p23.y = f2tf32(c[j][3]);
            *(uint2*)&P_s[m0 + g][j * 8 + 2 * tig] = p01;
            *(uint2*)&P_s[m0 + g + 8][j * 8 + 2 * tig] = p23;
        }
        __syncwarp();

        // O += P.V  (16 x 64 x 32)
        #pragma unroll
        for (int kc = 0; kc < 8; kc++) {
            int kk = kc * 8;
            unsigned af[4];
            af[0] = P_s[m0 + g][kk + tig];
            af[1] = P_s[m0 + g + 8][kk + tig];
            af[2] = P_s[m0 + g][kk + tig + 4];
            af[3] = P_s[m0 + g + 8][kk + tig + 4];
            unsigned vf[4][2];
            #pragma unroll
            for (int n = 0; n < 4; n++) {
                vf[n][0] = V_s[kk + tig][n * 8 + g];
                vf[n][1] = V_s[kk + tig + 4][n * 8 + g];
            }
            #pragma unroll
            for (int n = 0; n < 4; n++)
                mma_tf32(o[n], af, vf[n]);
        }
    }

    float inv0 = 1.0f / lrow[0];
    float inv1 = 1.0f / lrow[1];
    #pragma unroll
    for (int n = 0; n < 4; n++) {
        float2 w0, w1;
        w0.x = o[n][0] * inv0; w0.y = o[n][1] * inv0;
        w1.x = o[n][2] * inv1; w1.y = o[n][3] * inv1;
        int col = h * HD_ + n * 8 + 2 * tig;
        *(float2*)&ctx[(size_t)(b * LQ_ + q0 + m0 + g) * DIM_ + col] = w0;
        *(float2*)&ctx[(size_t)(b * LQ_ + q0 + m0 + g + 8) * DIM_ + col] = w1;
    }
}

// ---------------- launch ----------------
extern "C" void kernel_launch(void* const* d_in, const int* in_sizes, int n_in,
                              void* d_out, int out_size) {
    const float* q          = (const float*)d_in[0];
    const float* kv         = (const float*)d_in[1];
    const float* in_proj_w  = (const float*)d_in[2];
    const float* in_proj_b  = (const float*)d_in[3];
    const float* out_proj_w = (const float*)d_in[4];
    const float* out_proj_b = (const float*)d_in[5];
    const float* rel_bias   = (const float*)d_in[6];
    const float* mask_scale = (const float*)d_in[7];
    float* out = (float*)d_out;

    float *pQ, *pKV, *pM, *pC;
    cudaGetSymbolAddress((void**)&pQ,  g_Q);
    cudaGetSymbolAddress((void**)&pKV, g_KV);
    cudaGetSymbolAddress((void**)&pM,  g_mask);
    cudaGetSymbolAddress((void**)&pC,  g_ctx);

    const float attn_scale = 0.17677669529663687f;  // 1/sqrt(32)

    mask_kernel<<<(LQ_ * T_) / 256, 256>>>(rel_bias, mask_scale, pM);

    gemm_mma<<<dim3((B_ * LQ_) / 128, DIM_ / 128), 256>>>(
        q, in_proj_w, in_proj_b, pQ, DIM_, attn_scale);

    gemm_mma<<<dim3((B_ * T_) / 128, (2 * DIM_) / 128), 256>>>(
        kv, in_proj_w + DIM_ * DIM_, in_proj_b + DIM_, pKV, 2 * DIM_, 1.0f);

    attn_mma<<<dim3(LQ_ / 64, H_, B_), 128>>>(pQ, pKV, pM, pC);

    gemm_mma<<<dim3((B_ * LQ_) / 128, DIM_ / 128), 256>>>(
        pC, out_proj_w, out_proj_b, out, DIM_, 1.0f);
}

// round 5
// speedup vs baseline: 10.6858x; 1.4022x over previous
#include <cuda_runtime.h>
#include <cuda_fp16.h>
#include <math.h>
#include <stdint.h>

#define B_    8
#define H_    8
#define LQ_   512
#define T_    8192
#define DIM_  256
#define HD_   32
#define MAXREL_ 128

// ---------------- scratch ----------------
__device__ __half g_Qh[B_ * LQ_ * DIM_];        // scaled Q projection, fp16 (2 MB)
__device__ __half g_KVh[B_ * T_ * 2 * DIM_];    // fused K|V projection, fp16 (64 MB)
__device__ __half g_em[LQ_ * T_];               // exp(mask), fp16 (8 MB)
__device__ float  g_ctx[B_ * LQ_ * DIM_];       // attention context, fp32 (4 MB)

// ---------------- helpers ----------------
__device__ __forceinline__ void mma_f16(float c[4], const unsigned a[4], const unsigned b[2]) {
    asm volatile("mma.sync.aligned.m16n8k16.row.col.f32.f16.f16.f32 "
        "{%0,%1,%2,%3}, {%4,%5,%6,%7}, {%8,%9}, {%0,%1,%2,%3};"
        : "+f"(c[0]), "+f"(c[1]), "+f"(c[2]), "+f"(c[3])
        : "r"(a[0]), "r"(a[1]), "r"(a[2]), "r"(a[3]), "r"(b[0]), "r"(b[1]));
}
__device__ __forceinline__ unsigned h2u(__half2 h) { return *(unsigned*)&h; }

// ---------------- exp(mask) precompute ----------------
__global__ void emask_kernel(const float* __restrict__ rel_bias,
                             const float* __restrict__ mask_scale,
                             __half* __restrict__ em) {
    int idx = blockIdx.x * blockDim.x + threadIdx.x;
    int i = idx >> 13;
    int t = idx & (T_ - 1);
    const float step = 8191.0f / 511.0f;
    float tau = (float)i * step;
    float dt  = (float)t - tau;
    float dtc = fminf(fmaxf(dt, -(float)MAXREL_), (float)MAXREL_);
    int bi = (int)dtc + MAXREL_;
    float bias = rel_bias[bi];
    float z = dt * (1.0f / 64.0f);
    float lg = __logf(__expf(-0.5f * z * z) + 1e-6f);
    em[idx] = __float2half_rn(__expf(mask_scale[0] * (bias + lg)));
}

// ---------------- fp16 GEMM: out[r,c] = scale*(dot(A[r,:256], W[c,:256]) + bias[c]) ----------------
// A, W fp32 in gmem; staged fp16. Block tile 128x128, 8 warps (4m x 2n), warp tile 32x64.
template<bool OHALF>
__global__ void __launch_bounds__(256, 2) gemm16(const float* __restrict__ A,
                                                 const float* __restrict__ W,
                                                 const float* __restrict__ bias,
                                                 void* __restrict__ outp,
                                                 int ldo, float scale) {
    __shared__ unsigned As2[128][20];   // half2 units, k-chunk = 16 half2, stride 20
    __shared__ unsigned Ws2[128][20];
    int tid = threadIdx.x;
    int lane = tid & 31, warp = tid >> 5;
    int wm = warp >> 1, wn = warp & 1;
    int g = lane >> 2, tig = lane & 3;
    int row0 = blockIdx.x * 128, col0 = blockIdx.y * 128;

    float c[2][8][4];
    #pragma unroll
    for (int i = 0; i < 2; i++)
        #pragma unroll
        for (int j = 0; j < 8; j++)
            #pragma unroll
            for (int v = 0; v < 4; v++) c[i][j][v] = 0.0f;

    int sm  = tid >> 3;          // 0..31
    int sk4 = (tid & 7) * 4;     // float offset 0..28

    for (int k0 = 0; k0 < 256; k0 += 32) {
        __syncthreads();
        #pragma unroll
        for (int it = 0; it < 4; it++) {
            int r = sm + it * 32;
            float4 a4 = *(const float4*)&A[(size_t)(row0 + r) * 256 + k0 + sk4];
            float4 w4 = *(const float4*)&W[(size_t)(col0 + r) * 256 + k0 + sk4];
            __half2 a01 = __floats2half2_rn(a4.x, a4.y), a23 = __floats2half2_rn(a4.z, a4.w);
            __half2 w01 = __floats2half2_rn(w4.x, w4.y), w23 = __floats2half2_rn(w4.z, w4.w);
            uint2 ua; ua.x = h2u(a01); ua.y = h2u(a23);
            uint2 uw; uw.x = h2u(w01); uw.y = h2u(w23);
            *(uint2*)&As2[r][sk4 >> 1] = ua;
            *(uint2*)&Ws2[r][sk4 >> 1] = uw;
        }
        __syncthreads();
        #pragma unroll
        for (int kc = 0; kc < 2; kc++) {
            unsigned af[2][4], bf[8][2];
            #pragma unroll
            for (int i = 0; i < 2; i++) {
                int mr = wm * 32 + i * 16;
                af[i][0] = As2[mr + g][kc * 8 + tig];
                af[i][1] = As2[mr + g + 8][kc * 8 + tig];
                af[i][2] = As2[mr + g][kc * 8 + tig + 4];
                af[i][3] = As2[mr + g + 8][kc * 8 + tig + 4];
            }
            #pragma unroll
            for (int j = 0; j < 8; j++) {
                int nc = wn * 64 + j * 8;
                bf[j][0] = Ws2[nc + g][kc * 8 + tig];
                bf[j][1] = Ws2[nc + g][kc * 8 + tig + 4];
            }
            #pragma unroll
            for (int i = 0; i < 2; i++)
                #pragma unroll
                for (int j = 0; j < 8; j++)
                    mma_f16(c[i][j], af[i], bf[j]);
        }
    }

    #pragma unroll
    for (int j = 0; j < 8; j++) {
        int colg = col0 + wn * 64 + j * 8 + 2 * tig;
        float2 bv = *(const float2*)&bias[colg];
        #pragma unroll
        for (int i = 0; i < 2; i++) {
            int rowg = row0 + wm * 32 + i * 16 + g;
            float x0 = scale * (c[i][j][0] + bv.x);
            float y0 = scale * (c[i][j][1] + bv.y);
            float x1 = scale * (c[i][j][2] + bv.x);
            float y1 = scale * (c[i][j][3] + bv.y);
            if (OHALF) {
                __half* o = (__half*)outp;
                __half2 h0 = __floats2half2_rn(x0, y0);
                __half2 h1 = __floats2half2_rn(x1, y1);
                *(unsigned*)&o[(size_t)rowg * ldo + colg] = h2u(h0);
                *(unsigned*)&o[(size_t)(rowg + 8) * ldo + colg] = h2u(h1);
            } else {
                float* o = (float*)outp;
                float2 r0; r0.x = x0; r0.y = y0;
                float2 r1; r1.x = x1; r1.y = y1;
                *(float2*)&o[(size_t)rowg * ldo + colg] = r0;
                *(float2*)&o[(size_t)(rowg + 8) * ldo + colg] = r1;
            }
        }
    }
}

// ---------------- fp16 flash attention ----------------
// grid (Lq/64, H, B), 128 threads (4 warps). warp = (qg, kh): 32 q-rows x 32-key half.
__global__ void __launch_bounds__(128, 4) attn16(const __half* __restrict__ Qh,
                                                 const __half* __restrict__ KVh,
                                                 const __half* __restrict__ emh,
                                                 float* __restrict__ ctx) {
    __shared__ unsigned QK_s[2560];          // Q2 [64][20] + K2 [64][20]; aliased as Ored after loop
    __shared__ unsigned V2t[32][36];         // [d][t-half2], pairs (t even, t odd)
    __shared__ unsigned P2[4][32][20];       // per-warp P chunk, half2
    __shared__ float redm[2][64];
    __shared__ float redl[2][64];

    int tid = threadIdx.x;
    int lane = tid & 31, warp = tid >> 5;
    int qg = warp >> 1, kh = warp & 1;
    int g = lane >> 2, tig = lane & 3;
    int q0 = blockIdx.x * 64, h = blockIdx.y, b = blockIdx.z;

    #define Q2(r, c) QK_s[(r) * 20 + (c)]
    #define K2(r, c) QK_s[1280 + (r) * 20 + (c)]

    // stage Q once: 64 rows x 16 half2
    #pragma unroll
    for (int it = 0; it < 2; it++) {
        int idx = tid + it * 128;
        int r = idx >> 2, c4 = (idx & 3) * 4;
        uint4 v = *(const uint4*)&Qh[(size_t)(b * LQ_ + q0 + r) * DIM_ + h * HD_ + c4 * 2];
        *(uint4*)&Q2(r, c4) = v;
    }

    float m[2][2], l[2][2], o[2][4][4];
    #pragma unroll
    for (int i = 0; i < 2; i++)
        #pragma unroll
        for (int j = 0; j < 2; j++) { m[i][j] = -1e30f; l[i][j] = 0.0f; }
    #pragma unroll
    for (int i = 0; i < 2; i++)
        #pragma unroll
        for (int n = 0; n < 4; n++)
            #pragma unroll
            for (int v = 0; v < 4; v++) o[i][n][v] = 0.0f;

    for (int t0 = 0; t0 < T_; t0 += 64) {
        __syncthreads();                    // prior PV reads done; redl of prev tile valid
        if (t0 != 0) {
            #pragma unroll
            for (int mfr = 0; mfr < 2; mfr++)
                #pragma unroll
                for (int hi = 0; hi < 2; hi++) {
                    int lr = qg * 32 + mfr * 16 + hi * 8 + g;
                    l[mfr][hi] += redl[0][lr] + redl[1][lr];
                }
        }

        // stage K: 64 rows x 16 half2
        #pragma unroll
        for (int it = 0; it < 2; it++) {
            int idx = tid + it * 128;
            int r = idx >> 2, c4 = (idx & 3) * 4;
            uint4 v = *(const uint4*)&KVh[(size_t)(b * T_ + t0 + r) * (2 * DIM_) + h * HD_ + c4 * 2];
            *(uint4*)&K2(r, c4) = v;
        }
        // stage V transposed: V2t[d][t2] = (V[2*t2][d], V[2*t2+1][d])
        #pragma unroll
        for (int it = 0; it < 2; it++) {
            int t2 = (tid >> 3) + it * 16;
            int d4 = (tid & 7) * 4;
            const __half* vb0 = &KVh[(size_t)(b * T_ + t0 + 2 * t2) * (2 * DIM_) + DIM_ + h * HD_ + d4];
            uint2 va = *(const uint2*)vb0;
            uint2 vb = *(const uint2*)(vb0 + 2 * DIM_);
            V2t[d4 + 0][t2] = __byte_perm(va.x, vb.x, 0x5410);
            V2t[d4 + 1][t2] = __byte_perm(va.x, vb.x, 0x7632);
            V2t[d4 + 2][t2] = __byte_perm(va.y, vb.y, 0x5410);
            V2t[d4 + 3][t2] = __byte_perm(va.y, vb.y, 0x7632);
        }
        __syncthreads();

        // S = Q.K^T over warp chunk (32q x 32k): 2 kc x 2 mfr x 4 j
        float c[2][4][4] = {};
        #pragma unroll
        for (int kc = 0; kc < 2; kc++) {
            unsigned af[2][4], bf[4][2];
            #pragma unroll
            for (int mfr = 0; mfr < 2; mfr++) {
                int mr = qg * 32 + mfr * 16;
                af[mfr][0] = Q2(mr + g, kc * 8 + tig);
                af[mfr][1] = Q2(mr + g + 8, kc * 8 + tig);
                af[mfr][2] = Q2(mr + g, kc * 8 + tig + 4);
                af[mfr][3] = Q2(mr + g + 8, kc * 8 + tig + 4);
            }
            #pragma unroll
            for (int j = 0; j < 4; j++) {
                int kr = kh * 32 + j * 8 + g;
                bf[j][0] = K2(kr, kc * 8 + tig);
                bf[j][1] = K2(kr, kc * 8 + tig + 4);
            }
            #pragma unroll
            for (int mfr = 0; mfr < 2; mfr++)
                #pragma unroll
                for (int j = 0; j < 4; j++)
                    mma_f16(c[mfr][j], af[mfr], bf[j]);
        }

        // row max over own 32-col chunk, exchanged across kh pair
        #pragma unroll
        for (int mfr = 0; mfr < 2; mfr++)
            #pragma unroll
            for (int hi = 0; hi < 2; hi++) {
                float mx = c[mfr][0][hi * 2];
                #pragma unroll
                for (int j = 0; j < 4; j++)
                    mx = fmaxf(mx, fmaxf(c[mfr][j][hi * 2], c[mfr][j][hi * 2 + 1]));
                mx = fmaxf(mx, __shfl_xor_sync(0xffffffffu, mx, 1));
                mx = fmaxf(mx, __shfl_xor_sync(0xffffffffu, mx, 2));
                if (tig == 0) redm[kh][qg * 32 + mfr * 16 + hi * 8 + g] = mx;
            }
        __syncthreads();

        float al[2][2], psum[2][2];
        #pragma unroll
        for (int mfr = 0; mfr < 2; mfr++)
            #pragma unroll
            for (int hi = 0; hi < 2; hi++) {
                int lr = qg * 32 + mfr * 16 + hi * 8 + g;
                float mn = fmaxf(m[mfr][hi], fmaxf(redm[0][lr], redm[1][lr]));
                al[mfr][hi] = __expf(m[mfr][hi] - mn);
                m[mfr][hi] = mn;
                l[mfr][hi] *= al[mfr][hi];
                psum[mfr][hi] = 0.0f;
            }

        // p = exp(s - m) * emask; pack to P2
        #pragma unroll
        for (int mfr = 0; mfr < 2; mfr++) {
            int rowa = q0 + qg * 32 + mfr * 16 + g;
            const __half* ea = &emh[(size_t)rowa * T_ + t0 + kh * 32 + 2 * tig];
            const __half* eb = ea + (size_t)8 * T_;
            #pragma unroll
            for (int j = 0; j < 4; j++) {
                float2 ef0 = __half22float2(*(const __half2*)&ea[j * 8]);
                float2 ef1 = __half22float2(*(const __half2*)&eb[j * 8]);
                float p0 = __expf(c[mfr][j][0] - m[mfr][0]) * ef0.x;
                float p1 = __expf(c[mfr][j][1] - m[mfr][0]) * ef0.y;
                float p2 = __expf(c[mfr][j][2] - m[mfr][1]) * ef1.x;
                float p3 = __expf(c[mfr][j][3] - m[mfr][1]) * ef1.y;
                psum[mfr][0] += p0 + p1;
                psum[mfr][1] += p2 + p3;
                __half2 hp0 = __floats2half2_rn(p0, p1);
                __half2 hp1 = __floats2half2_rn(p2, p3);
                P2[warp][mfr * 16 + g][j * 4 + tig] = h2u(hp0);
                P2[warp][mfr * 16 + 8 + g][j * 4 + tig] = h2u(hp1);
            }
        }
        #pragma unroll
        for (int mfr = 0; mfr < 2; mfr++)
            #pragma unroll
            for (int hi = 0; hi < 2; hi++) {
                float ps = psum[mfr][hi];
                ps += __shfl_xor_sync(0xffffffffu, ps, 1);
                ps += __shfl_xor_sync(0xffffffffu, ps, 2);
                if (tig == 0) redl[kh][qg * 32 + mfr * 16 + hi * 8 + g] = ps;
            }

        // rescale O before accumulating this tile
        #pragma unroll
        for (int mfr = 0; mfr < 2; mfr++)
            #pragma unroll
            for (int n = 0; n < 4; n++) {
                o[mfr][n][0] *= al[mfr][0]; o[mfr][n][1] *= al[mfr][0];
                o[mfr][n][2] *= al[mfr][1]; o[mfr][n][3] *= al[mfr][1];
            }
        __syncwarp();

        // O += P.V over own key half (32k): 2 kc x 2 mfr x 4 n
        #pragma unroll
        for (int kc = 0; kc < 2; kc++) {
            unsigned af[2][4], bf[4][2];
            #pragma unroll
            for (int mfr = 0; mfr < 2; mfr++) {
                af[mfr][0] = P2[warp][mfr * 16 + g][kc * 8 + tig];
                af[mfr][1] = P2[warp][mfr * 16 + 8 + g][kc * 8 + tig];
                af[mfr][2] = P2[warp][mfr * 16 + g][kc * 8 + tig + 4];
                af[mfr][3] = P2[warp][mfr * 16 + 8 + g][kc * 8 + tig + 4];
            }
            #pragma unroll
            for (int n = 0; n < 4; n++) {
                bf[n][0] = V2t[n * 8 + g][kh * 16 + kc * 8 + tig];
                bf[n][1] = V2t[n * 8 + g][kh * 16 + kc * 8 + tig + 4];
            }
            #pragma unroll
            for (int mfr = 0; mfr < 2; mfr++)
                #pragma unroll
                for (int n = 0; n < 4; n++)
                    mma_f16(o[mfr][n], af[mfr], bf[n]);
        }
    }

    __syncthreads();                         // last PV done; redl valid; Q2/K2 free
    #pragma unroll
    for (int mfr = 0; mfr < 2; mfr++)
        #pragma unroll
        for (int hi = 0; hi < 2; hi++) {
            int lr = qg * 32 + mfr * 16 + hi * 8 + g;
            l[mfr][hi] += redl[0][lr] + redl[1][lr];
        }

    // combine kh partials via smem (stride 34 floats per row)
    float* Os = (float*)QK_s;
    if (kh == 1) {
        #pragma unroll
        for (int mfr = 0; mfr < 2; mfr++)
            #pragma unroll
            for (int n = 0; n < 4; n++) {
                int base0 = qg * 1088 + (mfr * 16 + g) * 34 + n * 8 + 2 * tig;
                int base1 = base0 + 8 * 34;
                float2 w0; w0.x = o[mfr][n][0]; w0.y = o[mfr][n][1];
                float2 w1; w1.x = o[mfr][n][2]; w1.y = o[mfr][n][3];
                *(float2*)&Os[base0] = w0;
                *(float2*)&Os[base1] = w1;
            }
    }
    __syncthreads();
    if (kh == 0) {
        #pragma unroll
        for (int mfr = 0; mfr < 2; mfr++) {
            float inv0 = 1.0f / l[mfr][0];
            float inv1 = 1.0f / l[mfr][1];
            #pragma unroll
            for (int n = 0; n < 4; n++) {
                int base0 = qg * 1088 + (mfr * 16 + g) * 34 + n * 8 + 2 * tig;
                int base1 = base0 + 8 * 34;
                float2 p0 = *(float2*)&Os[base0];
                float2 p1 = *(float2*)&Os[base1];
                float2 w0, w1;
                w0.x = (o[mfr][n][0] + p0.x) * inv0;
                w0.y = (o[mfr][n][1] + p0.y) * inv0;
                w1.x = (o[mfr][n][2] + p1.x) * inv1;
                w1.y = (o[mfr][n][3] + p1.y) * inv1;
                int r0 = b * LQ_ + q0 + qg * 32 + mfr * 16 + g;
                int col = h * HD_ + n * 8 + 2 * tig;
                *(float2*)&ctx[(size_t)r0 * DIM_ + col] = w0;
                *(float2*)&ctx[(size_t)(r0 + 8) * DIM_ + col] = w1;
            }
        }
    }
    #undef Q2
    #undef K2
}

// ---------------- launch ----------------
extern "C" void kernel_launch(void* const* d_in, const int* in_sizes, int n_in,
                              void* d_out, int out_size) {
    const float* q          = (const float*)d_in[0];
    const float* kv         = (const float*)d_in[1];
    const float* in_proj_w  = (const float*)d_in[2];
    const float* in_proj_b  = (const float*)d_in[3];
    const float* out_proj_w = (const float*)d_in[4];
    const float* out_proj_b = (const float*)d_in[5];
    const float* rel_bias   = (const float*)d_in[6];
    const float* mask_scale = (const float*)d_in[7];
    float* out = (float*)d_out;

    __half *pQ, *pKV, *pEM;
    float *pC;
    cudaGetSymbolAddress((void**)&pQ,  g_Qh);
    cudaGetSymbolAddress((void**)&pKV, g_KVh);
    cudaGetSymbolAddress((void**)&pEM, g_em);
    cudaGetSymbolAddress((void**)&pC,  g_ctx);

    const float attn_scale = 0.17677669529663687f;  // 1/sqrt(32)

    emask_kernel<<<(LQ_ * T_) / 256, 256>>>(rel_bias, mask_scale, pEM);

    gemm16<true><<<dim3((B_ * LQ_) / 128, DIM_ / 128), 256>>>(
        q, in_proj_w, in_proj_b, pQ, DIM_, attn_scale);

    gemm16<true><<<dim3((B_ * T_) / 128, (2 * DIM_) / 128), 256>>>(
        kv, in_proj_w + DIM_ * DIM_, in_proj_b + DIM_, pKV, 2 * DIM_, 1.0f);

    attn16<<<dim3(LQ_ / 64, H_, B_), 128>>>(pQ, pKV, pEM, pC);

    gemm16<false><<<dim3((B_ * LQ_) / 128, DIM_ / 128), 256>>>(
        pC, out_proj_w, out_proj_b, out, DIM_, 1.0f);
}

// round 6
// speedup vs baseline: 11.7301x; 1.0977x over previous
#include <cuda_runtime.h>
#include <cuda_fp16.h>
#include <math.h>
#include <stdint.h>

#define B_    8
#define H_    8
#define LQ_   512
#define T_    8192
#define DIM_  256
#define HD_   32
#define MAXREL_ 128

// ---------------- scratch ----------------
__device__ __half g_Qh[B_ * LQ_ * DIM_];
__device__ __half g_KVh[B_ * T_ * 2 * DIM_];
__device__ __half g_em[LQ_ * T_];
__device__ float  g_ctx[B_ * LQ_ * DIM_];

// ---------------- helpers ----------------
__device__ __forceinline__ void mma_f16(float c[4], const unsigned a[4], unsigned b0, unsigned b1) {
    asm volatile("mma.sync.aligned.m16n8k16.row.col.f32.f16.f16.f32 "
        "{%0,%1,%2,%3}, {%4,%5,%6,%7}, {%8,%9}, {%0,%1,%2,%3};"
        : "+f"(c[0]), "+f"(c[1]), "+f"(c[2]), "+f"(c[3])
        : "r"(a[0]), "r"(a[1]), "r"(a[2]), "r"(a[3]), "r"(b0), "r"(b1));
}
__device__ __forceinline__ unsigned h2u(__half2 h) { return *(unsigned*)&h; }
__device__ __forceinline__ uint32_t smem_u32(const void* p) {
    uint32_t a;
    asm("{ .reg .u64 t; cvta.to.shared.u64 t, %1; cvt.u32.u64 %0, t; }" : "=r"(a) : "l"(p));
    return a;
}
#define LDM_X4(r, addr) \
    asm volatile("ldmatrix.sync.aligned.m8n8.x4.shared.b16 {%0,%1,%2,%3}, [%4];" \
        : "=r"((r)[0]), "=r"((r)[1]), "=r"((r)[2]), "=r"((r)[3]) : "r"(addr))
#define LDM_X4T(r, addr) \
    asm volatile("ldmatrix.sync.aligned.m8n8.x4.trans.shared.b16 {%0,%1,%2,%3}, [%4];" \
        : "=r"((r)[0]), "=r"((r)[1]), "=r"((r)[2]), "=r"((r)[3]) : "r"(addr))

// ---------------- exp(mask) precompute ----------------
__global__ void emask_kernel(const float* __restrict__ rel_bias,
                             const float* __restrict__ mask_scale,
                             __half* __restrict__ em) {
    int idx = blockIdx.x * blockDim.x + threadIdx.x;
    int i = idx >> 13;
    int t = idx & (T_ - 1);
    const float step = 8191.0f / 511.0f;
    float tau = (float)i * step;
    float dt  = (float)t - tau;
    float dtc = fminf(fmaxf(dt, -(float)MAXREL_), (float)MAXREL_);
    int bi = (int)dtc + MAXREL_;
    float bias = rel_bias[bi];
    float z = dt * (1.0f / 64.0f);
    float lg = __logf(__expf(-0.5f * z * z) + 1e-6f);
    em[idx] = __float2half_rn(__expf(mask_scale[0] * (bias + lg)));
}

// ---------------- fp16 GEMM with ldmatrix fragment loads ----------------
// Block tile 128x128, 8 warps (4m x 2n), warp tile 32x64.
template<bool OHALF>
__global__ void __launch_bounds__(256, 2) gemm16(const float* __restrict__ A,
                                                 const float* __restrict__ W,
                                                 const float* __restrict__ bias,
                                                 void* __restrict__ outp,
                                                 int ldo, float scale) {
    __shared__ __align__(16) unsigned As2[128][20];   // half2 units, 80B rows
    __shared__ __align__(16) unsigned Ws2[128][20];
    int tid = threadIdx.x;
    int lane = tid & 31, warp = tid >> 5;
    int wm = warp >> 1, wn = warp & 1;
    int g = lane >> 2, tig = lane & 3;
    int row0 = blockIdx.x * 128, col0 = blockIdx.y * 128;
    uint32_t sbA = smem_u32(&As2[0][0]);
    uint32_t sbW = smem_u32(&Ws2[0][0]);

    float c[2][8][4];
    #pragma unroll
    for (int i = 0; i < 2; i++)
        #pragma unroll
        for (int j = 0; j < 8; j++)
            #pragma unroll
            for (int v = 0; v < 4; v++) c[i][j][v] = 0.0f;

    int sm  = tid >> 3;
    int sk4 = (tid & 7) * 4;

    // precomputed ldmatrix lane addresses (row/seg parts vary by kc only)
    uint32_t aArow = (uint32_t)(wm * 32 + (lane & 7) + ((lane >> 3) & 1) * 8);
    uint32_t aAseg = (uint32_t)(lane >> 4);
    uint32_t aBrow = (uint32_t)(wn * 64 + (lane >> 3) * 8 + (lane & 7));

    for (int k0 = 0; k0 < 256; k0 += 32) {
        __syncthreads();
        #pragma unroll
        for (int it = 0; it < 4; it++) {
            int r = sm + it * 32;
            float4 a4 = *(const float4*)&A[(size_t)(row0 + r) * 256 + k0 + sk4];
            float4 w4 = *(const float4*)&W[(size_t)(col0 + r) * 256 + k0 + sk4];
            __half2 a01 = __floats2half2_rn(a4.x, a4.y), a23 = __floats2half2_rn(a4.z, a4.w);
            __half2 w01 = __floats2half2_rn(w4.x, w4.y), w23 = __floats2half2_rn(w4.z, w4.w);
            uint2 ua; ua.x = h2u(a01); ua.y = h2u(a23);
            uint2 uw; uw.x = h2u(w01); uw.y = h2u(w23);
            *(uint2*)&As2[r][sk4 >> 1] = ua;
            *(uint2*)&Ws2[r][sk4 >> 1] = uw;
        }
        __syncthreads();
        #pragma unroll
        for (int kc = 0; kc < 2; kc++) {
            unsigned af0[4], af1[4];
            LDM_X4(af0, sbA + aArow * 80 + (kc * 2 + aAseg) * 16);
            LDM_X4(af1, sbA + (aArow + 16) * 80 + (kc * 2 + aAseg) * 16);
            unsigned b0a[4], b1a[4], b0b[4], b1b[4];
            uint32_t aB = sbW + aBrow * 80 + kc * 32;
            LDM_X4(b0a, aB);
            LDM_X4(b1a, aB + 16);
            LDM_X4(b0b, aB + 32 * 80);
            LDM_X4(b1b, aB + 32 * 80 + 16);
            #pragma unroll
            for (int j = 0; j < 8; j++) {
                unsigned bb0 = (j < 4) ? b0a[j] : b0b[j - 4];
                unsigned bb1 = (j < 4) ? b1a[j] : b1b[j - 4];
                mma_f16(c[0][j], af0, bb0, bb1);
                mma_f16(c[1][j], af1, bb0, bb1);
            }
        }
    }

    #pragma unroll
    for (int j = 0; j < 8; j++) {
        int colg = col0 + wn * 64 + j * 8 + 2 * tig;
        float2 bv = *(const float2*)&bias[colg];
        #pragma unroll
        for (int i = 0; i < 2; i++) {
            int rowg = row0 + wm * 32 + i * 16 + g;
            float x0 = scale * (c[i][j][0] + bv.x);
            float y0 = scale * (c[i][j][1] + bv.y);
            float x1 = scale * (c[i][j][2] + bv.x);
            float y1 = scale * (c[i][j][3] + bv.y);
            if (OHALF) {
                __half* o = (__half*)outp;
                *(unsigned*)&o[(size_t)rowg * ldo + colg] = h2u(__floats2half2_rn(x0, y0));
                *(unsigned*)&o[(size_t)(rowg + 8) * ldo + colg] = h2u(__floats2half2_rn(x1, y1));
            } else {
                float* o = (float*)outp;
                float2 r0; r0.x = x0; r0.y = y0;
                float2 r1; r1.x = x1; r1.y = y1;
                *(float2*)&o[(size_t)rowg * ldo + colg] = r0;
                *(float2*)&o[(size_t)(rowg + 8) * ldo + colg] = r1;
            }
        }
    }
}

// ---------------- fp16 flash attention, ldmatrix + register P ----------------
// grid (Lq/64, H, B), 128 threads (4 warps). warp = (qg, kh): 32 q-rows x 32-key half.
__global__ void __launch_bounds__(128, 4) attn16(const __half* __restrict__ Qh,
                                                 const __half* __restrict__ KVh,
                                                 const __half* __restrict__ emh,
                                                 float* __restrict__ ctx) {
    __shared__ __align__(16) unsigned KV_s[2][64][20];   // [0]=K [t][d], [1]=V [t][d], 80B rows
    __shared__ float redm[2][64];
    __shared__ float redl[2][64];

    int tid = threadIdx.x;
    int lane = tid & 31, warp = tid >> 5;
    int qg = warp >> 1, kh = warp & 1;
    int g = lane >> 2, tig = lane & 3;
    int q0 = blockIdx.x * 64, h = blockIdx.y, b = blockIdx.z;
    uint32_t sbK = smem_u32(&KV_s[0][0][0]);
    uint32_t sbV = smem_u32(&KV_s[1][0][0]);

    // Q A-frags resident in registers for the whole pass
    unsigned qf[2][2][4];
    #pragma unroll
    for (int mfr = 0; mfr < 2; mfr++) {
        const __half* qb0 = &Qh[(size_t)(b * LQ_ + q0 + qg * 32 + mfr * 16 + g) * DIM_ + h * HD_ + 2 * tig];
        #pragma unroll
        for (int kc = 0; kc < 2; kc++) {
            const __half* qb = qb0 + kc * 16;
            qf[mfr][kc][0] = *(const unsigned*)qb;
            qf[mfr][kc][1] = *(const unsigned*)(qb + 8 * DIM_);
            qf[mfr][kc][2] = *(const unsigned*)(qb + 8);
            qf[mfr][kc][3] = *(const unsigned*)(qb + 8 * DIM_ + 8);
        }
    }

    // ldmatrix lane-address components
    uint32_t kRow = (uint32_t)(kh * 32 + (lane >> 3) * 8 + (lane & 7));   // K: tile j = lane>>3
    uint32_t vRow = (uint32_t)(kh * 32 + (lane & 7));                     // V: + kc*16 (+8 for b1)
    uint32_t vSeg = (uint32_t)(lane >> 3) * 16;                           // V: n tile = lane>>3

    float m[2][2], l[2][2], o[2][4][4];
    #pragma unroll
    for (int i = 0; i < 2; i++)
        #pragma unroll
        for (int j = 0; j < 2; j++) { m[i][j] = -1e30f; l[i][j] = 0.0f; }
    #pragma unroll
    for (int i = 0; i < 2; i++)
        #pragma unroll
        for (int n = 0; n < 4; n++)
            #pragma unroll
            for (int v = 0; v < 4; v++) o[i][n][v] = 0.0f;

    for (int t0 = 0; t0 < T_; t0 += 64) {
        __syncthreads();                     // prior tile reads done; redl valid
        if (t0 != 0) {
            #pragma unroll
            for (int mfr = 0; mfr < 2; mfr++)
                #pragma unroll
                for (int hi = 0; hi < 2; hi++) {
                    int lr = qg * 32 + mfr * 16 + hi * 8 + g;
                    l[mfr][hi] += redl[0][lr] + redl[1][lr];
                }
        }

        // stage K and V tiles [t][d], 4KB each
        #pragma unroll
        for (int it = 0; it < 2; it++) {
            int i = tid + it * 128;
            int t = i >> 2, seg = i & 3;
            const __half* src = &KVh[(size_t)(b * T_ + t0 + t) * (2 * DIM_) + h * HD_];
            *(uint4*)((char*)&KV_s[0][t][0] + seg * 16) = *(const uint4*)(src + seg * 8);
            *(uint4*)((char*)&KV_s[1][t][0] + seg * 16) = *(const uint4*)(src + DIM_ + seg * 8);
        }
        __syncthreads();

        // S = Q.K^T over warp chunk (32q x 32k)
        float c[2][4][4];
        #pragma unroll
        for (int mfr = 0; mfr < 2; mfr++)
            #pragma unroll
            for (int j = 0; j < 4; j++)
                #pragma unroll
                for (int v = 0; v < 4; v++) c[mfr][j][v] = 0.0f;
        #pragma unroll
        for (int kc = 0; kc < 2; kc++) {
            unsigned kb0[4], kb1[4];
            uint32_t aB = sbK + kRow * 80 + kc * 32;
            LDM_X4(kb0, aB);
            LDM_X4(kb1, aB + 16);
            #pragma unroll
            for (int j = 0; j < 4; j++) {
                mma_f16(c[0][j], qf[0][kc], kb0[j], kb1[j]);
                mma_f16(c[1][j], qf[1][kc], kb0[j], kb1[j]);
            }
        }

        // row max over own 32-col chunk, exchanged across kh pair
        #pragma unroll
        for (int mfr = 0; mfr < 2; mfr++)
            #pragma unroll
            for (int hi = 0; hi < 2; hi++) {
                float mx = c[mfr][0][hi * 2];
                #pragma unroll
                for (int j = 0; j < 4; j++)
                    mx = fmaxf(mx, fmaxf(c[mfr][j][hi * 2], c[mfr][j][hi * 2 + 1]));
                mx = fmaxf(mx, __shfl_xor_sync(0xffffffffu, mx, 1));
                mx = fmaxf(mx, __shfl_xor_sync(0xffffffffu, mx, 2));
                if (tig == 0) redm[kh][qg * 32 + mfr * 16 + hi * 8 + g] = mx;
            }
        __syncthreads();

        float al[2][2], psum[2][2];
        #pragma unroll
        for (int mfr = 0; mfr < 2; mfr++)
            #pragma unroll
            for (int hi = 0; hi < 2; hi++) {
                int lr = qg * 32 + mfr * 16 + hi * 8 + g;
                float mn = fmaxf(m[mfr][hi], fmaxf(redm[0][lr], redm[1][lr]));
                al[mfr][hi] = __expf(m[mfr][hi] - mn);
                m[mfr][hi] = mn;
                l[mfr][hi] *= al[mfr][hi];
                psum[mfr][hi] = 0.0f;
            }

        // p = exp(s-m)*emask, packed directly into PV A-frags (registers only)
        unsigned pf[2][2][4];
        #pragma unroll
        for (int mfr = 0; mfr < 2; mfr++) {
            int rowa = q0 + qg * 32 + mfr * 16 + g;
            const __half* ea = &emh[(size_t)rowa * T_ + t0 + kh * 32 + 2 * tig];
            const __half* eb = ea + (size_t)8 * T_;
            #pragma unroll
            for (int j = 0; j < 4; j++) {
                float2 ef0 = __half22float2(*(const __half2*)&ea[j * 8]);
                float2 ef1 = __half22float2(*(const __half2*)&eb[j * 8]);
                float p0 = __expf(c[mfr][j][0] - m[mfr][0]) * ef0.x;
                float p1 = __expf(c[mfr][j][1] - m[mfr][0]) * ef0.y;
                float p2 = __expf(c[mfr][j][2] - m[mfr][1]) * ef1.x;
                float p3 = __expf(c[mfr][j][3] - m[mfr][1]) * ef1.y;
                psum[mfr][0] += p0 + p1;
                psum[mfr][1] += p2 + p3;
                pf[mfr][j >> 1][(j & 1) * 2 + 0] = h2u(__floats2half2_rn(p0, p1));
                pf[mfr][j >> 1][(j & 1) * 2 + 1] = h2u(__floats2half2_rn(p2, p3));
            }
        }
        #pragma unroll
        for (int mfr = 0; mfr < 2; mfr++)
            #pragma unroll
            for (int hi = 0; hi < 2; hi++) {
                float ps = psum[mfr][hi];
                ps += __shfl_xor_sync(0xffffffffu, ps, 1);
                ps += __shfl_xor_sync(0xffffffffu, ps, 2);
                if (tig == 0) redl[kh][qg * 32 + mfr * 16 + hi * 8 + g] = ps;
            }

        // rescale O
        #pragma unroll
        for (int mfr = 0; mfr < 2; mfr++)
            #pragma unroll
            for (int n = 0; n < 4; n++) {
                o[mfr][n][0] *= al[mfr][0]; o[mfr][n][1] *= al[mfr][0];
                o[mfr][n][2] *= al[mfr][1]; o[mfr][n][3] *= al[mfr][1];
            }

        // O += P.V over own key half: B-frags via ldmatrix.trans on [t][d] V
        #pragma unroll
        for (int kc = 0; kc < 2; kc++) {
            unsigned vb0[4], vb1[4];
            uint32_t aV = sbV + (vRow + kc * 16) * 80 + vSeg;
            LDM_X4T(vb0, aV);
            LDM_X4T(vb1, aV + 8 * 80);
            #pragma unroll
            for (int n = 0; n < 4; n++) {
                mma_f16(o[0][n], pf[0][kc], vb0[n], vb1[n]);
                mma_f16(o[1][n], pf[1][kc], vb0[n], vb1[n]);
            }
        }
    }

    __syncthreads();                          // last PV done; redl valid; KV_s free
    #pragma unroll
    for (int mfr = 0; mfr < 2; mfr++)
        #pragma unroll
        for (int hi = 0; hi < 2; hi++) {
            int lr = qg * 32 + mfr * 16 + hi * 8 + g;
            l[mfr][hi] += redl[0][lr] + redl[1][lr];
        }

    // combine kh partials via smem (aliased on KV_s), stride 34 floats per row
    float* Os = (float*)&KV_s[0][0][0];
    if (kh == 1) {
        #pragma unroll
        for (int mfr = 0; mfr < 2; mfr++)
            #pragma unroll
            for (int n = 0; n < 4; n++) {
                int base0 = qg * 1088 + (mfr * 16 + g) * 34 + n * 8 + 2 * tig;
                int base1 = base0 + 8 * 34;
                float2 w0; w0.x = o[mfr][n][0]; w0.y = o[mfr][n][1];
                float2 w1; w1.x = o[mfr][n][2]; w1.y = o[mfr][n][3];
                *(float2*)&Os[base0] = w0;
                *(float2*)&Os[base1] = w1;
            }
    }
    __syncthreads();
    if (kh == 0) {
        #pragma unroll
        for (int mfr = 0; mfr < 2; mfr++) {
            float inv0 = 1.0f / l[mfr][0];
            float inv1 = 1.0f / l[mfr][1];
            #pragma unroll
            for (int n = 0; n < 4; n++) {
                int base0 = qg * 1088 + (mfr * 16 + g) * 34 + n * 8 + 2 * tig;
                int base1 = base0 + 8 * 34;
                float2 p0 = *(float2*)&Os[base0];
                float2 p1 = *(float2*)&Os[base1];
                float2 w0, w1;
                w0.x = (o[mfr][n][0] + p0.x) * inv0;
                w0.y = (o[mfr][n][1] + p0.y) * inv0;
                w1.x = (o[mfr][n][2] + p1.x) * inv1;
                w1.y = (o[mfr][n][3] + p1.y) * inv1;
                int r0 = b * LQ_ + q0 + qg * 32 + mfr * 16 + g;
                int col = h * HD_ + n * 8 + 2 * tig;
                *(float2*)&ctx[(size_t)r0 * DIM_ + col] = w0;
                *(float2*)&ctx[(size_t)(r0 + 8) * DIM_ + col] = w1;
            }
        }
    }
}

// ---------------- launch ----------------
extern "C" void kernel_launch(void* const* d_in, const int* in_sizes, int n_in,
                              void* d_out, int out_size) {
    const float* q          = (const float*)d_in[0];
    const float* kv         = (const float*)d_in[1];
    const float* in_proj_w  = (const float*)d_in[2];
    const float* in_proj_b  = (const float*)d_in[3];
    const float* out_proj_w = (const float*)d_in[4];
    const float* out_proj_b = (const float*)d_in[5];
    const float* rel_bias   = (const float*)d_in[6];
    const float* mask_scale = (const float*)d_in[7];
    float* out = (float*)d_out;

    __half *pQ, *pKV, *pEM;
    float *pC;
    cudaGetSymbolAddress((void**)&pQ,  g_Qh);
    cudaGetSymbolAddress((void**)&pKV, g_KVh);
    cudaGetSymbolAddress((void**)&pEM, g_em);
    cudaGetSymbolAddress((void**)&pC,  g_ctx);

    const float attn_scale = 0.17677669529663687f;  // 1/sqrt(32)

    emask_kernel<<<(LQ_ * T_) / 256, 256>>>(rel_bias, mask_scale, pEM);

    gemm16<true><<<dim3((B_ * LQ_) / 128, DIM_ / 128), 256>>>(
        q, in_proj_w, in_proj_b, pQ, DIM_, attn_scale);

    gemm16<true><<<dim3((B_ * T_) / 128, (2 * DIM_) / 128), 256>>>(
        kv, in_proj_w + DIM_ * DIM_, in_proj_b + DIM_, pKV, 2 * DIM_, 1.0f);

    attn16<<<dim3(LQ_ / 64, H_, B_), 128>>>(pQ, pKV, pEM, pC);

    gemm16<false><<<dim3((B_ * LQ_) / 128, DIM_ / 128), 256>>>(
        pC, out_proj_w, out_proj_b, out, DIM_, 1.0f);
}